// round 1
// baseline (speedup 1.0000x reference)
#include <cuda_runtime.h>
#include <cmath>

// ---------------------------------------------------------------------------
// ResidualConvLSTM2D  (B=4, T=16, H=W=64, Cin=32, F=64)
// Round 1: fp32 shared-memory direct conv baseline.
// ---------------------------------------------------------------------------

#define B_   4
#define T_   16
#define HH   64
#define WW   64
#define HW   4096         // 64*64
#define CIN_X 32
#define F_   64
#define COUT 256          // 4*F
#define FRAMES 64         // B*T

// Scratch (allocation-free rule: __device__ globals)
__device__ float g_xplanar[FRAMES * CIN_X * HW];   // 33.5 MB  [frame][ci][pix]
__device__ float g_zx[FRAMES * COUT * HW];         // 268 MB   [frame][oc][pix]  (= conv(x,Wx)+b)
__device__ float g_zs[B_ * COUT * HW];             // 16.8 MB  [b][oc][pix]      (= conv(h,Wh))
__device__ float g_h [B_ * F_ * HW];               // 4.2 MB   [b][f][pix]
__device__ float g_c [B_ * F_ * HW];               // 4.2 MB   [b][f][pix]

// ---------------------------------------------------------------------------
// Zero h and c state (must happen every launch: deterministic re-run)
// ---------------------------------------------------------------------------
__global__ void zero_hc_kernel() {
    int g = blockIdx.x * 256 + threadIdx.x;
    if (g < B_ * F_ * HW) { g_h[g] = 0.f; g_c[g] = 0.f; }
}

// ---------------------------------------------------------------------------
// Pack x: NHWC (frame, pix, ci) -> planar (frame, ci, pix), smem transpose.
// grid (16 pixblocks, 64 frames), 256 threads
// ---------------------------------------------------------------------------
__global__ void pack_x_kernel(const float* __restrict__ x) {
    __shared__ float s[256 * 33];   // padded: stride 33 kills bank conflicts
    int frame = blockIdx.y;
    int pix0  = blockIdx.x * 256;
    const float* src = x + (size_t)frame * (HW * CIN_X) + (size_t)pix0 * CIN_X;
    for (int i = threadIdx.x; i < 256 * CIN_X; i += 256) {
        int p = i >> 5, ci = i & 31;          // read coalesced (linear over src)
        s[p * 33 + ci] = src[i];
    }
    __syncthreads();
    for (int i = threadIdx.x; i < 256 * CIN_X; i += 256) {
        int p = i & 255, ci = i >> 8;         // write coalesced (pix fastest)
        g_xplanar[((size_t)frame * CIN_X + ci) * HW + pix0 + p] = s[p * 33 + ci];
    }
}

// ---------------------------------------------------------------------------
// Residual: out[frame][pix][f] = sum_ci x[frame][pix][ci]*Wp[ci][f] + bp[f]
// Initializes ALL of d_out (poisoned by harness). grid 1024, 256 threads.
// ---------------------------------------------------------------------------
__global__ void residual_kernel(const float* __restrict__ x,
                                const float* __restrict__ Wp,
                                const float* __restrict__ bp,
                                float* __restrict__ out) {
    __shared__ float sW[CIN_X * F_];
    __shared__ float sb[F_];
    for (int i = threadIdx.x; i < CIN_X * F_; i += 256) sW[i] = Wp[i];
    if (threadIdx.x < F_) sb[threadIdx.x] = bp[threadIdx.x];
    __syncthreads();

    int g = blockIdx.x * 256 + threadIdx.x;      // one (frame,pix) per thread
    float xv[CIN_X];
    const float4* xp = (const float4*)(x + (size_t)g * CIN_X);
    #pragma unroll
    for (int i = 0; i < CIN_X / 4; i++) {
        float4 v = xp[i];
        xv[4*i] = v.x; xv[4*i+1] = v.y; xv[4*i+2] = v.z; xv[4*i+3] = v.w;
    }
    float* op = out + (size_t)g * F_;
    #pragma unroll 4
    for (int f = 0; f < F_; f++) {
        float a = sb[f];
        #pragma unroll
        for (int ci = 0; ci < CIN_X; ci++)
            a = fmaf(xv[ci], sW[ci * F_ + f], a);   // sW broadcast across lanes
        op[f] = a;
    }
}

// ---------------------------------------------------------------------------
// 3x3 SAME conv, planar in/out, weights (3,3,CIN,256).
// MODE 0: in=g_xplanar (CIN=32), out=g_zx, +bias   (all 64 frames)
// MODE 1: in=g_h       (CIN=64), out=g_zs, no bias (4 frames, per step)
// Block: 256 thr = 32x8; tile 32(w) x 16(h) pixels; 32 out-channels/block.
// Per thread: 2 pixels x 32 oc = 64 fp32 accumulators.
// grid: (8 tiles, frames, 8 oc-chunks)
// ---------------------------------------------------------------------------
template<int CIN, int MODE>
__global__ __launch_bounds__(256, 2)
void conv3x3_kernel(const float* __restrict__ wsrc, const float* __restrict__ bias) {
    __shared__ float s_in[8 * 18 * 34];   // 8 ci x 18 rows x 34 cols (halo)
    __shared__ float s_w [9 * 8 * 32];    // 9 taps x 8 ci x 32 oc

    const float* in  = (MODE == 0) ? g_xplanar : g_h;
    float*       out = (MODE == 0) ? g_zx      : g_zs;

    int tileX = blockIdx.x & 1;           // 0..1  (32-wide)
    int tileY = blockIdx.x >> 1;          // 0..3  (16-tall)
    int frame = blockIdx.y;
    int oc0   = blockIdx.z * 32;
    int tid   = threadIdx.x;
    int tx = tid & 31, ty = tid >> 5;
    int gx0 = tileX * 32, gy0 = tileY * 16;

    float acc0[32], acc1[32];
    #pragma unroll
    for (int i = 0; i < 32; i++) { acc0[i] = 0.f; acc1[i] = 0.f; }

    for (int c0 = 0; c0 < CIN; c0 += 8) {
        // load input patch (zero-fill halo via predication)
        for (int i = tid; i < 8 * 18 * 34; i += 256) {
            int xx = i % 34; int r = i / 34; int yy = r % 18; int ci = r / 18;
            int gy = gy0 + yy - 1, gx = gx0 + xx - 1;
            float v = 0.f;
            if ((unsigned)gy < 64u && (unsigned)gx < 64u)
                v = in[(((size_t)frame * CIN + c0 + ci) << 12) + gy * WW + gx];
            s_in[i] = v;
        }
        // load weight chunk
        for (int i = tid; i < 9 * 8 * 32; i += 256) {
            int oc = i & 31, ci = (i >> 5) & 7, tap = i >> 8;
            s_w[i] = wsrc[(size_t)(tap * CIN + c0 + ci) * COUT + oc0 + oc];
        }
        __syncthreads();

        #pragma unroll 1
        for (int tap = 0; tap < 9; tap++) {
            int dy = tap / 3, dx = tap - dy * 3;
            #pragma unroll
            for (int ci = 0; ci < 8; ci++) {
                float in0 = s_in[(ci * 18 + ty     + dy) * 34 + tx + dx];
                float in1 = s_in[(ci * 18 + ty + 8 + dy) * 34 + tx + dx];
                const float* wp = &s_w[(tap * 8 + ci) * 32];
                #pragma unroll
                for (int oc = 0; oc < 32; oc++) {
                    float w = wp[oc];
                    acc0[oc] = fmaf(in0, w, acc0[oc]);
                    acc1[oc] = fmaf(in1, w, acc1[oc]);
                }
            }
        }
        __syncthreads();
    }

    int p0 = (gy0 + ty) * WW + gx0 + tx;
    int p1 = p0 + 8 * WW;
    size_t obase = ((size_t)frame * COUT + oc0) << 12;
    #pragma unroll
    for (int oc = 0; oc < 32; oc++) {
        float bv = (MODE == 0) ? bias[oc0 + oc] : 0.f;
        out[obase + ((size_t)oc << 12) + p0] = acc0[oc] + bv;   // coalesced (tx fastest)
        out[obase + ((size_t)oc << 12) + p1] = acc1[oc] + bv;
    }
}

// ---------------------------------------------------------------------------
// Gates + state update + residual add.  One step t.
// Thread handles (b, pix, 16 f's).  grid 256, 256 threads.
// ---------------------------------------------------------------------------
__global__ void gate_kernel(float* __restrict__ out, int t) {
    int g   = blockIdx.x * 256 + threadIdx.x;   // < 65536
    int q   = g & 3;                            // which 16-f slice
    int pix = (g >> 2) & 4095;
    int b   = g >> 14;
    int f0  = q * 16;
    int frame = b * T_ + t;

    size_t zxb = ((size_t)frame * COUT) << 12;
    size_t zsb = ((size_t)b * COUT) << 12;
    size_t cb  = ((size_t)b * F_)   << 12;
    float* op  = out + (((size_t)frame << 12) + pix) * F_;

    #pragma unroll
    for (int j = 0; j < 16; j++) {
        int f = f0 + j;
        float zi = g_zx[zxb + ((size_t)(f        ) << 12) + pix] + g_zs[zsb + ((size_t)(f        ) << 12) + pix];
        float zf = g_zx[zxb + ((size_t)(f +   F_ ) << 12) + pix] + g_zs[zsb + ((size_t)(f +   F_ ) << 12) + pix];
        float zc = g_zx[zxb + ((size_t)(f + 2*F_ ) << 12) + pix] + g_zs[zsb + ((size_t)(f + 2*F_ ) << 12) + pix];
        float zo = g_zx[zxb + ((size_t)(f + 3*F_ ) << 12) + pix] + g_zs[zsb + ((size_t)(f + 3*F_ ) << 12) + pix];

        float ig = __saturatef(fmaf(0.2f, zi, 0.5f));   // keras hard_sigmoid
        float fg = __saturatef(fmaf(0.2f, zf, 0.5f));
        float og = __saturatef(fmaf(0.2f, zo, 0.5f));

        float cold = g_c[cb + ((size_t)f << 12) + pix];
        float cnew = fmaf(fg, cold, ig * tanhf(zc));
        float h    = og * tanhf(cnew);

        g_c[cb + ((size_t)f << 12) + pix] = cnew;
        g_h[cb + ((size_t)f << 12) + pix] = h;
        op[f] = op[f] + h;                               // residual already there
    }
}

// ---------------------------------------------------------------------------
// Launch
// ---------------------------------------------------------------------------
extern "C" void kernel_launch(void* const* d_in, const int* in_sizes, int n_in,
                              void* d_out, int out_size) {
    const float* x  = (const float*)d_in[0];   // (4,16,64,64,32)
    const float* Wx = (const float*)d_in[1];   // (3,3,32,256)
    const float* Wh = (const float*)d_in[2];   // (3,3,64,256)
    const float* b  = (const float*)d_in[3];   // (256,)
    const float* Wp = (const float*)d_in[4];   // (1,1,32,64)
    const float* bp = (const float*)d_in[5];   // (64,)
    float* out = (float*)d_out;                // (4,16,64,64,64)

    // state reset (determinism across replays)
    zero_hc_kernel<<<(B_ * F_ * HW + 255) / 256, 256>>>();

    // pack x to planar
    pack_x_kernel<<<dim3(16, FRAMES), 256>>>(x);

    // residual branch initializes all of d_out
    residual_kernel<<<(FRAMES * HW) / 256, 256>>>(x, Wp, bp, out);

    // input-to-gates conv for all 64 frames at once (+bias)
    conv3x3_kernel<CIN_X, 0><<<dim3(8, FRAMES, 8), 256>>>(Wx, b);

    // sequential recurrence
    for (int t = 0; t < T_; t++) {
        conv3x3_kernel<F_, 1><<<dim3(8, B_, 8), 256>>>(Wh, nullptr);
        gate_kernel<<<256, 256>>>(out, t);
    }
}

// round 3
// speedup vs baseline: 1.0436x; 1.0436x over previous
#include <cuda_runtime.h>
#include <cmath>

// ---------------------------------------------------------------------------
// ResidualConvLSTM2D  (B=4, T=16, H=W=64, Cin=32, F=64)
// Round 2: packed fp32x2 FFMA2 conv (2x fp32 throughput path on sm_103a).
// ---------------------------------------------------------------------------

#define B_   4
#define T_   16
#define HH   64
#define WW   64
#define HW   4096         // 64*64
#define CIN_X 32
#define F_   64
#define COUT 256          // 4*F
#define FRAMES 64         // B*T

typedef unsigned long long u64;

// packed f32x2 fma: d = a*b + c on both 32-bit halves (SASS FFMA2)
#define FMA_F32X2(d, a, b, c) \
    asm("fma.rn.f32x2 %0, %1, %2, %3;" : "=l"(d) : "l"(a), "l"(b), "l"(c))

__device__ __forceinline__ u64 bcast_f32x2(float v) {
    u64 r; unsigned u = __float_as_uint(v);
    asm("mov.b64 %0, {%1, %1};" : "=l"(r) : "r"(u));
    return r;
}
__device__ __forceinline__ void unpack_f32x2(u64 v, float& lo, float& hi) {
    unsigned a, b;
    asm("mov.b64 {%0, %1}, %2;" : "=r"(a), "=r"(b) : "l"(v));
    lo = __uint_as_float(a); hi = __uint_as_float(b);
}

// Scratch (allocation-free rule: __device__ globals)
__device__ float g_xplanar[FRAMES * CIN_X * HW];   // [frame][ci][pix]
__device__ float g_zx[FRAMES * COUT * HW];         // [frame][oc][pix]  (= conv(x,Wx)+b)
__device__ float g_zs[B_ * COUT * HW];             // [b][oc][pix]      (= conv(h,Wh))
__device__ float g_h [B_ * F_ * HW];               // [b][f][pix]
__device__ float g_c [B_ * F_ * HW];               // [b][f][pix]

// ---------------------------------------------------------------------------
__global__ void zero_hc_kernel() {
    int g = blockIdx.x * 256 + threadIdx.x;
    if (g < B_ * F_ * HW) { g_h[g] = 0.f; g_c[g] = 0.f; }
}

// ---------------------------------------------------------------------------
// Pack x: NHWC (frame, pix, ci) -> planar (frame, ci, pix), smem transpose.
// ---------------------------------------------------------------------------
__global__ void pack_x_kernel(const float* __restrict__ x) {
    __shared__ float s[256 * 33];
    int frame = blockIdx.y;
    int pix0  = blockIdx.x * 256;
    const float* src = x + (size_t)frame * (HW * CIN_X) + (size_t)pix0 * CIN_X;
    for (int i = threadIdx.x; i < 256 * CIN_X; i += 256) {
        int p = i >> 5, ci = i & 31;
        s[p * 33 + ci] = src[i];
    }
    __syncthreads();
    for (int i = threadIdx.x; i < 256 * CIN_X; i += 256) {
        int p = i & 255, ci = i >> 8;
        g_xplanar[((size_t)frame * CIN_X + ci) * HW + pix0 + p] = s[p * 33 + ci];
    }
}

// ---------------------------------------------------------------------------
// Residual: out[frame][pix][f] = sum_ci x[frame][pix][ci]*Wp[ci][f] + bp[f]
// ---------------------------------------------------------------------------
__global__ void residual_kernel(const float* __restrict__ x,
                                const float* __restrict__ Wp,
                                const float* __restrict__ bp,
                                float* __restrict__ out) {
    __shared__ float sW[CIN_X * F_];
    __shared__ float sb[F_];
    for (int i = threadIdx.x; i < CIN_X * F_; i += 256) sW[i] = Wp[i];
    if (threadIdx.x < F_) sb[threadIdx.x] = bp[threadIdx.x];
    __syncthreads();

    int g = blockIdx.x * 256 + threadIdx.x;
    float xv[CIN_X];
    const float4* xp = (const float4*)(x + (size_t)g * CIN_X);
    #pragma unroll
    for (int i = 0; i < CIN_X / 4; i++) {
        float4 v = xp[i];
        xv[4*i] = v.x; xv[4*i+1] = v.y; xv[4*i+2] = v.z; xv[4*i+3] = v.w;
    }
    float* op = out + (size_t)g * F_;
    #pragma unroll 4
    for (int f = 0; f < F_; f++) {
        float a = sb[f];
        #pragma unroll
        for (int ci = 0; ci < CIN_X; ci++)
            a = fmaf(xv[ci], sW[ci * F_ + f], a);
        op[f] = a;
    }
}

// ---------------------------------------------------------------------------
// 3x3 SAME conv, planar in/out, weights (3,3,CIN,256), FFMA2 inner loop.
// MODE 0: in=g_xplanar (CIN=32), out=g_zx, +bias   (all 64 frames)
// MODE 1: in=g_h       (CIN=64), out=g_zs, no bias (4 frames, per step)
// Block: 256 thr = 32x8; tile 32(w) x 16(h) pixels; 32 out-channels/block.
// Per thread: 2 pixels x 16 packed oc-pairs = 32 x f32x2 accumulators.
// ---------------------------------------------------------------------------
template<int CIN, int MODE>
__global__ __launch_bounds__(256, 2)
void conv3x3_kernel(const float* __restrict__ wsrc, const float* __restrict__ bias) {
    __shared__ float s_in[8 * 18 * 34];   // 8 ci x 18 rows x 34 cols (halo)
    __shared__ float s_w [9 * 8 * 32];    // 9 taps x 8 ci x 32 oc (16B aligned rows)

    const float* in  = (MODE == 0) ? g_xplanar : g_h;
    float*       out = (MODE == 0) ? g_zx      : g_zs;

    int tileX = blockIdx.x & 1;
    int tileY = blockIdx.x >> 1;
    int frame = blockIdx.y;
    int oc0   = blockIdx.z * 32;
    int tid   = threadIdx.x;
    int tx = tid & 31, ty = tid >> 5;
    int gx0 = tileX * 32, gy0 = tileY * 16;

    u64 acc0[16], acc1[16];               // packed (oc even, oc odd) pairs
    #pragma unroll
    for (int i = 0; i < 16; i++) { acc0[i] = 0ull; acc1[i] = 0ull; }

    for (int c0 = 0; c0 < CIN; c0 += 8) {
        for (int i = tid; i < 8 * 18 * 34; i += 256) {
            int xx = i % 34; int r = i / 34; int yy = r % 18; int ci = r / 18;
            int gy = gy0 + yy - 1, gx = gx0 + xx - 1;
            float v = 0.f;
            if ((unsigned)gy < 64u && (unsigned)gx < 64u)
                v = in[(((size_t)frame * CIN + c0 + ci) << 12) + gy * WW + gx];
            s_in[i] = v;
        }
        for (int i = tid; i < 9 * 8 * 32; i += 256) {
            int oc = i & 31, ci = (i >> 5) & 7, tap = i >> 8;
            s_w[i] = wsrc[(size_t)(tap * CIN + c0 + ci) * COUT + oc0 + oc];
        }
        __syncthreads();

        #pragma unroll 1
        for (int tap = 0; tap < 9; tap++) {
            int dy = tap / 3, dx = tap - dy * 3;
            #pragma unroll
            for (int ci = 0; ci < 8; ci++) {
                u64 i0 = bcast_f32x2(s_in[(ci * 18 + ty     + dy) * 34 + tx + dx]);
                u64 i1 = bcast_f32x2(s_in[(ci * 18 + ty + 8 + dy) * 34 + tx + dx]);
                const ulonglong2* wp = (const ulonglong2*)&s_w[(tap * 8 + ci) * 32];
                #pragma unroll
                for (int j = 0; j < 8; j++) {
                    ulonglong2 w2 = wp[j];           // 4 weights = 2 packed pairs
                    FMA_F32X2(acc0[2*j  ], i0, w2.x, acc0[2*j  ]);
                    FMA_F32X2(acc0[2*j+1], i0, w2.y, acc0[2*j+1]);
                    FMA_F32X2(acc1[2*j  ], i1, w2.x, acc1[2*j  ]);
                    FMA_F32X2(acc1[2*j+1], i1, w2.y, acc1[2*j+1]);
                }
            }
        }
        __syncthreads();
    }

    int p0 = (gy0 + ty) * WW + gx0 + tx;
    int p1 = p0 + 8 * WW;
    size_t obase = ((size_t)frame * COUT + oc0) << 12;
    #pragma unroll
    for (int j = 0; j < 16; j++) {
        float a0lo, a0hi, a1lo, a1hi;
        unpack_f32x2(acc0[j], a0lo, a0hi);
        unpack_f32x2(acc1[j], a1lo, a1hi);
        int oce = 2 * j, oco = 2 * j + 1;
        float bve = (MODE == 0) ? bias[oc0 + oce] : 0.f;
        float bvo = (MODE == 0) ? bias[oc0 + oco] : 0.f;
        out[obase + ((size_t)oce << 12) + p0] = a0lo + bve;
        out[obase + ((size_t)oco << 12) + p0] = a0hi + bvo;
        out[obase + ((size_t)oce << 12) + p1] = a1lo + bve;
        out[obase + ((size_t)oco << 12) + p1] = a1hi + bvo;
    }
}

// ---------------------------------------------------------------------------
// Gates + state update + residual add.  One step t.
// ---------------------------------------------------------------------------
__global__ void gate_kernel(float* __restrict__ out, int t) {
    int g   = blockIdx.x * 256 + threadIdx.x;   // < 65536
    int q   = g & 3;
    int pix = (g >> 2) & 4095;
    int b   = g >> 14;
    int f0  = q * 16;
    int frame = b * T_ + t;

    size_t zxb = ((size_t)frame * COUT) << 12;
    size_t zsb = ((size_t)b * COUT) << 12;
    size_t cb  = ((size_t)b * F_)   << 12;
    float* op  = out + (((size_t)frame << 12) + pix) * F_;

    #pragma unroll
    for (int j = 0; j < 16; j++) {
        int f = f0 + j;
        float zi = g_zx[zxb + ((size_t)(f        ) << 12) + pix] + g_zs[zsb + ((size_t)(f        ) << 12) + pix];
        float zf = g_zx[zxb + ((size_t)(f +   F_ ) << 12) + pix] + g_zs[zsb + ((size_t)(f +   F_ ) << 12) + pix];
        float zc = g_zx[zxb + ((size_t)(f + 2*F_ ) << 12) + pix] + g_zs[zsb + ((size_t)(f + 2*F_ ) << 12) + pix];
        float zo = g_zx[zxb + ((size_t)(f + 3*F_ ) << 12) + pix] + g_zs[zsb + ((size_t)(f + 3*F_ ) << 12) + pix];

        float ig = __saturatef(fmaf(0.2f, zi, 0.5f));
        float fg = __saturatef(fmaf(0.2f, zf, 0.5f));
        float og = __saturatef(fmaf(0.2f, zo, 0.5f));

        float cold = g_c[cb + ((size_t)f << 12) + pix];
        float cnew = fmaf(fg, cold, ig * tanhf(zc));
        float h    = og * tanhf(cnew);

        g_c[cb + ((size_t)f << 12) + pix] = cnew;
        g_h[cb + ((size_t)f << 12) + pix] = h;
        op[f] = op[f] + h;
    }
}

// ---------------------------------------------------------------------------
extern "C" void kernel_launch(void* const* d_in, const int* in_sizes, int n_in,
                              void* d_out, int out_size) {
    const float* x  = (const float*)d_in[0];   // (4,16,64,64,32)
    const float* Wx = (const float*)d_in[1];   // (3,3,32,256)
    const float* Wh = (const float*)d_in[2];   // (3,3,64,256)
    const float* b  = (const float*)d_in[3];   // (256,)
    const float* Wp = (const float*)d_in[4];   // (1,1,32,64)
    const float* bp = (const float*)d_in[5];   // (64,)
    float* out = (float*)d_out;                // (4,16,64,64,64)

    zero_hc_kernel<<<(B_ * F_ * HW + 255) / 256, 256>>>();
    pack_x_kernel<<<dim3(16, FRAMES), 256>>>(x);
    residual_kernel<<<(FRAMES * HW) / 256, 256>>>(x, Wp, bp, out);
    conv3x3_kernel<CIN_X, 0><<<dim3(8, FRAMES, 8), 256>>>(Wx, b);

    for (int t = 0; t < T_; t++) {
        conv3x3_kernel<F_, 1><<<dim3(8, B_, 8), 256>>>(Wh, nullptr);
        gate_kernel<<<256, 256>>>(out, t);
    }
}